// round 6
// baseline (speedup 1.0000x reference)
#include <cuda_runtime.h>
#include <cuda_bf16.h>
#include <cstdint>

// ============================================================================
// ValueNetwork via mma.sync m16n8k16 bf16 (3-term split), sm_103 base target.
// Per CTA: NB=6 batch elems = 120 token rows padded to M=128.
// 16 warps = 8 M-tiles x 2 N-halves. Activations in fragment-native bf16x2
// pair layout: word[pair*136 + row]  (136 % 32 == 8 -> conflict-free frags).
// ============================================================================

#define NTOK 20
#define D_IN 13
#define NB 6
#define NTHREADS 512

// ---- SMEM layout (byte offsets) ----
#define SLOTA_H 0        // 80 pairs * 136 * 4 = 43520
#define SLOTA_L 43520
#define SLOTB_H 87040    // 56 pairs -> 30464
#define SLOTB_L 117504
#define WBUF    147968   // 35840 (max weight image, L2)
#define FREG    183808   // 50 cols * 128 rows * 4 = 25600
#define BIAS_OFF 209408  // 160 f
#define G_OFF    210048  // 600 f
#define GATT_OFF 212448  // 672 f
#define ATT_OFF  215136  // 128 f
#define JNT_OFF  215648  // 336 f
#define M3A_OFF  216992  // 900 f
#define M3B_OFF  220592  // 600 f
#define SMEM_BYTES 222992

// ---- packed weight images (bytes, hi at off, lo at off+LO_BASE) ----
#define IMG_L1 0        // Npad160 Kpad16  : 5120
#define IMG_L2 5120     // Npad112 Kpad160 : 35840
#define IMG_L3 40960    // Npad112 Kpad112 : 25088
#define IMG_L4 66048    // Npad64  Kpad112 : 14336
#define IMG_L5 80384    // Npad112 Kpad112 : 25088
#define IMG_L6 105472   // Npad112 Kpad112 : 25088
#define LO_BASE 130560
__device__ __align__(16) unsigned char g_wpack[2 * LO_BASE];

// ============================================================================

__device__ __forceinline__ void pack_pair(float v0, float v1,
                                          uint32_t& hi, uint32_t& lo) {
    __nv_bfloat16 h0 = __float2bfloat16(v0);
    __nv_bfloat16 h1 = __float2bfloat16(v1);
    __nv_bfloat16 l0 = __float2bfloat16(v0 - __bfloat162float(h0));
    __nv_bfloat16 l1 = __float2bfloat16(v1 - __bfloat162float(h1));
    hi = ((uint32_t)(*(uint16_t*)&h1) << 16) | (uint32_t)(*(uint16_t*)&h0);
    lo = ((uint32_t)(*(uint16_t*)&l1) << 16) | (uint32_t)(*(uint16_t*)&l0);
}
__device__ __forceinline__ float bf_lo(uint32_t u) {
    return __uint_as_float(u << 16);
}
__device__ __forceinline__ float bf_hi(uint32_t u) {
    return __uint_as_float(u & 0xFFFF0000u);
}

__device__ __forceinline__ void stage_bytes(char* pool, const unsigned char* src,
                                            int dstOff, int bytes, int tid) {
    float4* d = (float4*)(pool + dstOff);
    const float4* s = (const float4*)src;
    const int n = bytes >> 4;
    for (int i = tid; i < n; i += NTHREADS) d[i] = s[i];
}

// one 3-term-split pass over K for this warp's tile set
template <int NT, int NK>
__device__ __forceinline__ void mma_pass(const char* pool, int srcOff,
                                         float acc[NT][4], int mt, int nh, int lane) {
    const uint32_t* A = (const uint32_t*)(pool + srcOff);
    const uint2* Bv = (const uint2*)(pool + WBUF);
    const int lm = lane & 3, ld4 = lane >> 2;
#pragma unroll
    for (int ks = 0; ks < NK; ++ks) {
        const int p0 = ks * 8 + lm;
        const int r0 = mt * 16 + ld4;
        const uint32_t a0 = A[p0 * 136 + r0];
        const uint32_t a1 = A[p0 * 136 + r0 + 8];
        const uint32_t a2 = A[(p0 + 4) * 136 + r0];
        const uint32_t a3 = A[(p0 + 4) * 136 + r0 + 8];
#pragma unroll
        for (int t = 0; t < NT; ++t) {
            const int tn = nh * NT + t;
            const uint2 b = Bv[(tn * NK + ks) * 32 + lane];
            asm volatile(
                "mma.sync.aligned.m16n8k16.row.col.f32.bf16.bf16.f32 "
                "{%0,%1,%2,%3}, {%4,%5,%6,%7}, {%8,%9}, {%0,%1,%2,%3};"
                : "+f"(acc[t][0]), "+f"(acc[t][1]),
                  "+f"(acc[t][2]), "+f"(acc[t][3])
                : "r"(a0), "r"(a1), "r"(a2), "r"(a3), "r"(b.x), "r"(b.y));
        }
    }
}

// EPI: 0 = relu -> bf16 hi/lo slot; 1 = relu + gatt -> slot; 2 = linear -> FREG
template <int NT, int NK, int EPI>
__device__ void run_layer(char* pool, int srcH, int srcL, int dstH, int dstL,
                          int imgOff, int imgBytes, int tid) {
    const int wid = tid >> 5, lane = tid & 31;
    const int mt = wid & 7, nh = wid >> 3;
    float acc[NT][4];
#pragma unroll
    for (int t = 0; t < NT; ++t)
        acc[t][0] = acc[t][1] = acc[t][2] = acc[t][3] = 0.f;

    stage_bytes(pool, g_wpack + imgOff, WBUF, imgBytes, tid);
    __syncthreads();
    mma_pass<NT, NK>(pool, srcH, acc, mt, nh, lane);   // Ah * Bh
    mma_pass<NT, NK>(pool, srcL, acc, mt, nh, lane);   // Al * Bh
    __syncthreads();
    stage_bytes(pool, g_wpack + LO_BASE + imgOff, WBUF, imgBytes, tid);
    __syncthreads();
    mma_pass<NT, NK>(pool, srcH, acc, mt, nh, lane);   // Ah * Bl

    const float* bias = (const float*)(pool + BIAS_OFF);
    const float* gatt = (const float*)(pool + GATT_OFF);
    const int rlo = mt * 16 + (lane >> 2), rhi = rlo + 8;
    int blo = rlo / NTOK; if (blo > NB - 1) blo = NB - 1;
    int bhi = rhi / NTOK; if (bhi > NB - 1) bhi = NB - 1;
#pragma unroll
    for (int t = 0; t < NT; ++t) {
        const int c0 = (nh * NT + t) * 8 + (lane & 3) * 2;
        float v00 = acc[t][0] + bias[c0], v01 = acc[t][1] + bias[c0 + 1];
        float v10 = acc[t][2] + bias[c0], v11 = acc[t][3] + bias[c0 + 1];
        if (EPI == 2) {
            float* F = (float*)(pool + FREG);
            if (c0 < 50)     { F[c0 * 128 + rlo] = v00;       F[c0 * 128 + rhi] = v10; }
            if (c0 + 1 < 50) { F[(c0 + 1) * 128 + rlo] = v01; F[(c0 + 1) * 128 + rhi] = v11; }
        } else {
            if (EPI == 1) {
                v00 += gatt[blo * 112 + c0]; v01 += gatt[blo * 112 + c0 + 1];
                v10 += gatt[bhi * 112 + c0]; v11 += gatt[bhi * 112 + c0 + 1];
            }
            v00 = fmaxf(v00, 0.f); v01 = fmaxf(v01, 0.f);
            v10 = fmaxf(v10, 0.f); v11 = fmaxf(v11, 0.f);
            uint32_t hA, lA, hB, lB;
            pack_pair(v00, v01, hA, lA);
            pack_pair(v10, v11, hB, lB);
            const int p = c0 >> 1;
            uint32_t* DH = (uint32_t*)(pool + dstH);
            uint32_t* DL = (uint32_t*)(pool + dstL);
            DH[p * 136 + rlo] = hA; DL[p * 136 + rlo] = lA;
            DH[p * 136 + rhi] = hB; DL[p * 136 + rhi] = lB;
        }
    }
    __syncthreads();
}

// ============================================================================
// prep: pack weights into B-fragment lane order (hi/lo split)
// slot = ((tn*NK + ks)*32 + lane); holds b0 = {W[k0],W[k0+1]}, b1 = {+8,+9} @ col n
// ============================================================================
#define TOTAL_SLOTS 16320
__global__ void vnet_prep(const float* m1w0, const float* m1w1, const float* m2w0,
                          const float* m2w1, const float* aw0, const float* aw1) {
    const int i = blockIdx.x * blockDim.x + threadIdx.x;
    if (i >= TOTAL_SLOTS) return;
    const float* W; int K, N, NKl, off, lin;
    if      (i < 640)   { W = m1w0; K = 13;  N = 150; NKl = 1;  off = IMG_L1; lin = i; }
    else if (i < 5120)  { W = m1w1; K = 150; N = 100; NKl = 10; off = IMG_L2; lin = i - 640; }
    else if (i < 8256)  { W = m2w0; K = 100; N = 100; NKl = 7;  off = IMG_L3; lin = i - 5120; }
    else if (i < 10048) { W = m2w1; K = 100; N = 50;  NKl = 7;  off = IMG_L4; lin = i - 8256; }
    else if (i < 13184) { W = aw0;  K = 100; N = 100; NKl = 7;  off = IMG_L5; lin = i - 10048; }
    else                { W = aw1;  K = 100; N = 100; NKl = 7;  off = IMG_L6; lin = i - 13184; }
    const int l = lin & 31, q = lin >> 5;
    const int ks = q % NKl, tn = q / NKl;
    const int n = tn * 8 + (l >> 2);
    const int k0 = ks * 16 + (l & 3) * 2;
    float v[4];
#pragma unroll
    for (int j = 0; j < 4; ++j) {
        const int k = k0 + (j >> 1) * 8 + (j & 1);
        v[j] = (k < K && n < N) ? W[k * N + n] : 0.f;
    }
    uint32_t h0, l0, h1, l1;
    pack_pair(v[0], v[1], h0, l0);
    pack_pair(v[2], v[3], h1, l1);
    const size_t bo = (size_t)off + (size_t)lin * 8;
    *(uint32_t*)(g_wpack + bo)     = h0;
    *(uint32_t*)(g_wpack + bo + 4) = h1;
    *(uint32_t*)(g_wpack + LO_BASE + bo)     = l0;
    *(uint32_t*)(g_wpack + LO_BASE + bo + 4) = l1;
}

// ============================================================================
// main kernel
// ============================================================================
__global__ __launch_bounds__(NTHREADS, 1)
void vnet_main(const float* __restrict__ state,
               const float* __restrict__ m1b0, const float* __restrict__ m1b1,
               const float* __restrict__ m2b0, const float* __restrict__ m2b1,
               const float* __restrict__ aw0,  const float* __restrict__ ab0,
               const float* __restrict__ ab1,  const float* __restrict__ aw2,
               const float* __restrict__ ab2,
               const float* __restrict__ m3w0, const float* __restrict__ m3b0,
               const float* __restrict__ m3w1, const float* __restrict__ m3b1,
               const float* __restrict__ m3w2, const float* __restrict__ m3b2,
               const float* __restrict__ m3w3, const float* __restrict__ m3b3,
               float* __restrict__ out, const int Btot) {
    extern __shared__ char pool[];
    const int tid = threadIdx.x;
    const int ctaB0 = blockIdx.x * NB;
    float* sBias = (float*)(pool + BIAS_OFF);

    // ---- stage X into slotB (pairs 0..7, rows 0..127) ----
    {
        uint32_t* XH = (uint32_t*)(pool + SLOTB_H);
        uint32_t* XL = (uint32_t*)(pool + SLOTB_L);
        for (int idx = tid; idx < 128 * 8; idx += NTHREADS) {
            const int r = idx & 127, p = idx >> 7;
            const int b = r / NTOK, n = r - b * NTOK;
            const int gb = ctaB0 + b;
            float v0 = 0.f, v1 = 0.f;
            if (r < NB * NTOK && gb < Btot) {
                const float* sp = state + ((long)gb * NTOK + n) * D_IN;
                const int k0 = p * 2;
                if (k0 < D_IN) v0 = sp[k0];
                if (k0 + 1 < D_IN) v1 = sp[k0 + 1];
            }
            uint32_t h, l;
            pack_pair(v0, v1, h, l);
            XH[p * 136 + r] = h;
            XL[p * 136 + r] = l;
        }
        if (tid < 160) sBias[tid] = (tid < 150) ? m1b0[tid] : 0.f;
    }
    // (sync inside run_layer staging covers the writes above)

    // L1: X @ m1w0 -> h1 (slotA, Npad=160)
    run_layer<10, 1, 0>(pool, SLOTB_H, SLOTB_L, SLOTA_H, SLOTA_L, IMG_L1, 5120, tid);

    if (tid < 112) sBias[tid] = (tid < 100) ? m1b1[tid] : 0.f;
    // L2: h1 @ m1w1 -> h (slotB, Npad=112)
    run_layer<7, 10, 0>(pool, SLOTA_H, SLOTA_L, SLOTB_H, SLOTB_L, IMG_L2, 35840, tid);

    // ---- g = mean_n h (fp32 from hi+lo) ----
    {
        const uint32_t* HH = (const uint32_t*)(pool + SLOTB_H);
        const uint32_t* HL = (const uint32_t*)(pool + SLOTB_L);
        float* g = (float*)(pool + G_OFF);
        for (int idx = tid; idx < NB * 100; idx += NTHREADS) {
            const int b = idx / 100, k = idx - b * 100;
            const int p = k >> 1, odd = k & 1;
            float s = 0.f;
#pragma unroll
            for (int n = 0; n < NTOK; ++n) {
                const int w = p * 136 + b * NTOK + n;
                s += odd ? (bf_hi(HH[w]) + bf_hi(HL[w]))
                         : (bf_lo(HH[w]) + bf_lo(HL[w]));
            }
            g[idx] = s * (1.f / NTOK);
        }
    }
    __syncthreads();
    // ---- gatt[b][c] = sum_k g[b][k] * aw0[100+k][c], cols padded to 112 ----
    {
        const float* g = (const float*)(pool + G_OFF);
        float* ga = (float*)(pool + GATT_OFF);
        for (int idx = tid; idx < NB * 112; idx += NTHREADS) {
            const int b = idx / 112, c = idx - b * 112;
            float s = 0.f;
            if (c < 100) {
                const float* gp = g + b * 100;
#pragma unroll 4
                for (int k = 0; k < 100; ++k) s += gp[k] * aw0[(100 + k) * 100 + c];
            }
            ga[idx] = s;
        }
    }
    __syncthreads();

    if (tid < 112) sBias[tid] = (tid < 100) ? m2b0[tid] : 0.f;
    // L3: h @ m2w0 -> f1 (slotA)
    run_layer<7, 7, 0>(pool, SLOTB_H, SLOTB_L, SLOTA_H, SLOTA_L, IMG_L3, 25088, tid);

    if (tid < 64) sBias[tid] = (tid < 50) ? m2b1[tid] : 0.f;
    // L4: f1 @ m2w1 -> f (FREG fp32, linear)
    run_layer<4, 7, 2>(pool, SLOTA_H, SLOTA_L, 0, 0, IMG_L4, 14336, tid);

    if (tid < 112) sBias[tid] = (tid < 100) ? ab0[tid] : 0.f;
    // L5: h @ aw0[0:100] (+gatt) -> a1 (slotA)
    run_layer<7, 7, 1>(pool, SLOTB_H, SLOTB_L, SLOTA_H, SLOTA_L, IMG_L5, 25088, tid);

    if (tid < 112) sBias[tid] = (tid < 100) ? ab1[tid] : 0.f;
    // L6: a1 @ aw1 -> a2 (slotB)
    run_layer<7, 7, 0>(pool, SLOTA_H, SLOTA_L, SLOTB_H, SLOTB_L, IMG_L6, 25088, tid);

    // ---- attention scalar per row: att = a2 . aw2 + ab2 ----
    if (tid < 128) {
        const uint32_t* AH = (const uint32_t*)(pool + SLOTB_H);
        const uint32_t* AL = (const uint32_t*)(pool + SLOTB_L);
        float s = ab2[0];
#pragma unroll 5
        for (int p = 0; p < 50; ++p) {
            const int w = p * 136 + tid;
            const float v0 = bf_lo(AH[w]) + bf_lo(AL[w]);
            const float v1 = bf_hi(AH[w]) + bf_hi(AL[w]);
            s += v0 * aw2[2 * p] + v1 * aw2[2 * p + 1];
        }
        ((float*)(pool + ATT_OFF))[tid] = s;
    }
    __syncthreads();

    // ---- weighted = sum_n f * att ; joint = [self_state, weighted] ----
    {
        float* sJ = (float*)(pool + JNT_OFF);
        const float* F = (const float*)(pool + FREG);
        const float* att = (const float*)(pool + ATT_OFF);
        for (int idx = tid; idx < NB * 50; idx += NTHREADS) {
            const int b = idx / 50, c = idx - b * 50;
            float s = 0.f;
#pragma unroll
            for (int n = 0; n < NTOK; ++n)
                s += F[c * 128 + b * NTOK + n] * att[b * NTOK + n];
            sJ[b * 56 + 6 + c] = s;
        }
        if (tid < NB * 6) {
            const int b = tid / 6, d = tid - b * 6;
            const int gb = ctaB0 + b;
            sJ[b * 56 + d] = (gb < Btot) ? state[(long)gb * NTOK * D_IN + d] : 0.f;
        }
    }
    __syncthreads();

    // ---- m3 head (fp32 CUDA cores): 56 -> 150 -> 100 -> 100 -> 1 ----
    {
        float* sJ = (float*)(pool + JNT_OFF);
        float* sA = (float*)(pool + M3A_OFF);
        float* sB = (float*)(pool + M3B_OFF);
        for (int idx = tid; idx < NB * 150; idx += NTHREADS) {
            const int b = idx / 150, j = idx - b * 150;
            float s = m3b0[j];
#pragma unroll 4
            for (int k = 0; k < 56; ++k) s += sJ[b * 56 + k] * m3w0[k * 150 + j];
            sA[idx] = fmaxf(s, 0.f);
        }
        __syncthreads();
        for (int idx = tid; idx < NB * 100; idx += NTHREADS) {
            const int b = idx / 100, j = idx - b * 100;
            float s = m3b1[j];
#pragma unroll 4
            for (int k = 0; k < 150; ++k) s += sA[b * 150 + k] * m3w1[k * 100 + j];
            sB[idx] = fmaxf(s, 0.f);
        }
        __syncthreads();
        for (int idx = tid; idx < NB * 100; idx += NTHREADS) {
            const int b = idx / 100, j = idx - b * 100;
            float s = m3b2[j];
#pragma unroll 4
            for (int k = 0; k < 100; ++k) s += sB[b * 100 + k] * m3w2[k * 100 + j];
            sA[idx] = fmaxf(s, 0.f);
        }
        __syncthreads();
        if (tid < NB) {
            const int gb = ctaB0 + tid;
            if (gb < Btot) {
                float s = m3b3[0];
#pragma unroll 4
                for (int k = 0; k < 100; ++k) s += sA[tid * 100 + k] * m3w3[k];
                out[gb] = s;
            }
        }
    }
}

extern "C" void kernel_launch(void* const* d_in, const int* in_sizes, int n_in,
                              void* d_out, int out_size) {
    const float* state = (const float*)d_in[0];
    const float* m1w0 = (const float*)d_in[1],  *m1b0 = (const float*)d_in[2];
    const float* m1w1 = (const float*)d_in[3],  *m1b1 = (const float*)d_in[4];
    const float* m2w0 = (const float*)d_in[5],  *m2b0 = (const float*)d_in[6];
    const float* m2w1 = (const float*)d_in[7],  *m2b1 = (const float*)d_in[8];
    const float* aw0  = (const float*)d_in[9],  *ab0  = (const float*)d_in[10];
    const float* aw1  = (const float*)d_in[11], *ab1  = (const float*)d_in[12];
    const float* aw2  = (const float*)d_in[13], *ab2  = (const float*)d_in[14];
    const float* m3w0 = (const float*)d_in[15], *m3b0 = (const float*)d_in[16];
    const float* m3w1 = (const float*)d_in[17], *m3b1 = (const float*)d_in[18];
    const float* m3w2 = (const float*)d_in[19], *m3b2 = (const float*)d_in[20];
    const float* m3w3 = (const float*)d_in[21], *m3b3 = (const float*)d_in[22];
    float* out = (float*)d_out;
    const int Btot = in_sizes[0] / (NTOK * D_IN);

    vnet_prep<<<(TOTAL_SLOTS + 255) / 256, 256>>>(m1w0, m1w1, m2w0, m2w1, aw0, aw1);

    static int attrSet = 0;
    if (!attrSet) {
        cudaFuncSetAttribute(vnet_main,
                             cudaFuncAttributeMaxDynamicSharedMemorySize, SMEM_BYTES);
        attrSet = 1;
    }
    const int grid = (Btot + NB - 1) / NB;
    vnet_main<<<grid, NTHREADS, SMEM_BYTES>>>(
        state, m1b0, m1b1, m2b0, m2b1, aw0, ab0, ab1, aw2, ab2,
        m3w0, m3b0, m3w1, m3b1, m3w2, m3b2, m3w3, m3b3, out, Btot);
}

// round 8
// speedup vs baseline: 2.6177x; 2.6177x over previous
#include <cuda_runtime.h>
#include <cuda_bf16.h>
#include <cstdint>

// ============================================================================
// ValueNetwork via mma.sync m16n8k16 bf16 (3-term split), two-kernel version.
// Kernel A (token net): 256 thr, NB=3 batches (M=64 rows), 2 CTAs/SM.
// Kernel B (m3 head):   512 thr, 128 batches/CTA (M=128), 1 wave GEMM.
// Weight images packed ks-outer for contiguous K-chunked staging.
// ============================================================================

#define NTOK 20
#define D_IN 13
#define NB 3

// ---- packed weight images (bytes; hi at off, lo at off+LO_BASE) ----
#define IMG_L1  0        // m1w0: TILES20 NK1   (5120 B)
#define IMG_L2  5120     // m1w1: TILES14 NK10  (35840)
#define IMG_L3  40960    // m2w0: TILES14 NK7   (25088)
#define IMG_L4  66048    // m2w1: TILES8  NK7   (14336)
#define IMG_L5  80384    // aw0 head: T14 NK7   (25088)
#define IMG_L6  105472   // aw1: T14 NK7        (25088)
#define IMG_M30 130560   // m3w0: T20 NK4       (20480)
#define IMG_M31 151040   // m3w1: T14 NK10      (35840)
#define IMG_M32 186880   // m3w2: T14 NK7       (25088)
#define LO_BASE 211968
__device__ __align__(16) unsigned char g_wpack[2 * LO_BASE];
__device__ __align__(16) uint32_t g_awt[100 * 112];     // aw0 tail, (hi16|lo16)
__device__ __align__(16) float g_joint[16384 * 56];     // inter-kernel scratch

// ---- kernel A SMEM (bytes), RS_A = 72 words ----
#define RS_A 72
#define SA_H 0          // 80 pairs * 72 * 4 = 23040
#define SA_L 23040
#define SB_H 46080      // 56 pairs -> 16128
#define SB_L 62208
#define WBUF_A 78336    // 25088
#define WCAP_A 25088
#define BIAS_A 103424
#define G_A    104064
#define GATT_A 105264
#define ATT_A  106608
#define AW2_A  106864
#define WTD_A  107264
#define SMEM_A 108032

// ---- kernel B SMEM, RS_B = 136 words ----
#define RS_B 136
#define BA_H 0          // 80 pairs * 136 * 4 = 43520
#define BA_L 43520
#define BB_H 87040      // 32 pairs -> 17408
#define BB_L 104448
#define WBUF_B 121856   // 35840
#define WCAP_B 35840
#define BIAS_B 157696
#define W3_B   158336
#define SMEM_B 158736

// ============================================================================
__device__ __forceinline__ void pack_pair(float v0, float v1,
                                          uint32_t& hi, uint32_t& lo) {
    __nv_bfloat16 h0 = __float2bfloat16(v0);
    __nv_bfloat16 h1 = __float2bfloat16(v1);
    __nv_bfloat16 l0 = __float2bfloat16(v0 - __bfloat162float(h0));
    __nv_bfloat16 l1 = __float2bfloat16(v1 - __bfloat162float(h1));
    hi = ((uint32_t)(*(uint16_t*)&h1) << 16) | (uint32_t)(*(uint16_t*)&h0);
    lo = ((uint32_t)(*(uint16_t*)&l1) << 16) | (uint32_t)(*(uint16_t*)&l0);
}
__device__ __forceinline__ float bf_lo(uint32_t u) { return __uint_as_float(u << 16); }
__device__ __forceinline__ float bf_hi(uint32_t u) { return __uint_as_float(u & 0xFFFF0000u); }

__device__ __forceinline__ void hmma4(float* a, uint32_t a0, uint32_t a1,
                                      uint32_t a2, uint32_t a3, uint2 b) {
    asm volatile(
        "mma.sync.aligned.m16n8k16.row.col.f32.bf16.bf16.f32 "
        "{%0,%1,%2,%3}, {%4,%5,%6,%7}, {%8,%9}, {%0,%1,%2,%3};"
        : "+f"(a[0]), "+f"(a[1]), "+f"(a[2]), "+f"(a[3])
        : "r"(a0), "r"(a1), "r"(a2), "r"(a3), "r"(b.x), "r"(b.y));
}

template <int NTHR>
__device__ __forceinline__ void stage_bytes(char* pool, const unsigned char* src,
                                            int dstOff, int bytes, int tid) {
    float4* d = (float4*)(pool + dstOff);
    const float4* s = (const float4*)src;
    const int n = bytes >> 4;
    for (int i = tid; i < n; i += NTHR) d[i] = s[i];
}

// one K-chunk of MMAs. DUAL=1: Ah*B and Al*B (B-fragment reused); DUAL=0: Ah*B.
template <int NT, int TILES, int RS, int DUAL>
__device__ __forceinline__ void mma_chunk(const char* pool, int srcH, int srcL,
                                          int wbufOff, float (*acc)[4],
                                          int ks0, int nks, int mt, int nh, int lane) {
    const uint32_t* AH = (const uint32_t*)(pool + srcH);
    const uint32_t* AL = (const uint32_t*)(pool + srcL);
    const uint2* Bv = (const uint2*)(pool + wbufOff);
    const int lm = lane & 3, r0 = mt * 16 + (lane >> 2);
    for (int ksl = 0; ksl < nks; ++ksl) {
        const int p0 = (ks0 + ksl) * 8 + lm;
        const uint32_t ah0 = AH[p0 * RS + r0], ah1 = AH[p0 * RS + r0 + 8];
        const uint32_t ah2 = AH[(p0 + 4) * RS + r0], ah3 = AH[(p0 + 4) * RS + r0 + 8];
        uint32_t al0 = 0, al1 = 0, al2 = 0, al3 = 0;
        if (DUAL) {
            al0 = AL[p0 * RS + r0]; al1 = AL[p0 * RS + r0 + 8];
            al2 = AL[(p0 + 4) * RS + r0]; al3 = AL[(p0 + 4) * RS + r0 + 8];
        }
#pragma unroll
        for (int t = 0; t < NT; ++t) {
            const uint2 b = Bv[(ksl * TILES + nh * NT + t) * 32 + lane];
            hmma4(acc[t], ah0, ah1, ah2, ah3, b);
            if (DUAL) hmma4(acc[t], al0, al1, al2, al3, b);
        }
    }
}

// full fused layer. EPI: 0 = relu->pairs, 1 = relu+gatt->pairs, 2 = f*att atomic.
template <int NTHR, int RS, int MTILES, int NT, int NK, int TILES, int EPI>
__device__ void run_layer(char* pool, int srcH, int srcL, int dstH, int dstL,
                          int imgOff, int wbufOff, int wbufCap,
                          int biasOff, int auxOff, int aux2Off, int tid) {
    const int wid = tid >> 5, lane = tid & 31;
    const int mt = wid % MTILES, nh = wid / MTILES;
    float acc[NT][4];
#pragma unroll
    for (int t = 0; t < NT; ++t)
        acc[t][0] = acc[t][1] = acc[t][2] = acc[t][3] = 0.f;
    const int bpk = TILES * 256;
    const int ksCap = wbufCap / bpk;
    for (int k0 = 0; k0 < NK; k0 += ksCap) {
        const int nks = (NK - k0 < ksCap) ? NK - k0 : ksCap;
        stage_bytes<NTHR>(pool, g_wpack + imgOff + (size_t)k0 * bpk, wbufOff, nks * bpk, tid);
        __syncthreads();
        mma_chunk<NT, TILES, RS, 1>(pool, srcH, srcL, wbufOff, acc, k0, nks, mt, nh, lane);
        __syncthreads();
    }
    for (int k0 = 0; k0 < NK; k0 += ksCap) {
        const int nks = (NK - k0 < ksCap) ? NK - k0 : ksCap;
        stage_bytes<NTHR>(pool, g_wpack + LO_BASE + imgOff + (size_t)k0 * bpk, wbufOff, nks * bpk, tid);
        __syncthreads();
        mma_chunk<NT, TILES, RS, 0>(pool, srcH, srcH, wbufOff, acc, k0, nks, mt, nh, lane);
        __syncthreads();
    }
    const float* bias = (const float*)(pool + biasOff);
    const int rlo = mt * 16 + (lane >> 2), rhi = rlo + 8;
    if (EPI == 2) {
        const float* att = (const float*)(pool + auxOff);
        float* wtd = (float*)(pool + aux2Off);
        const float alo = att[rlo], ahi = att[rhi];
        int blo = rlo / NTOK; if (blo > NB - 1) blo = NB - 1;
        int bhi = rhi / NTOK; if (bhi > NB - 1) bhi = NB - 1;
#pragma unroll
        for (int t = 0; t < NT; ++t) {
            const int c0 = (nh * NT + t) * 8 + (lane & 3) * 2;
            if (c0 < 50) {
                atomicAdd(&wtd[blo * 64 + c0], (acc[t][0] + bias[c0]) * alo);
                atomicAdd(&wtd[bhi * 64 + c0], (acc[t][2] + bias[c0]) * ahi);
            }
            if (c0 + 1 < 50) {
                atomicAdd(&wtd[blo * 64 + c0 + 1], (acc[t][1] + bias[c0 + 1]) * alo);
                atomicAdd(&wtd[bhi * 64 + c0 + 1], (acc[t][3] + bias[c0 + 1]) * ahi);
            }
        }
    } else {
        const float* ga = (const float*)(pool + auxOff);
        int blo = 0, bhi = 0;
        if (EPI == 1) {
            blo = rlo / NTOK; if (blo > NB - 1) blo = NB - 1;
            bhi = rhi / NTOK; if (bhi > NB - 1) bhi = NB - 1;
        }
        uint32_t* DH = (uint32_t*)(pool + dstH);
        uint32_t* DL = (uint32_t*)(pool + dstL);
#pragma unroll
        for (int t = 0; t < NT; ++t) {
            const int c0 = (nh * NT + t) * 8 + (lane & 3) * 2;
            float v00 = acc[t][0] + bias[c0], v01 = acc[t][1] + bias[c0 + 1];
            float v10 = acc[t][2] + bias[c0], v11 = acc[t][3] + bias[c0 + 1];
            if (EPI == 1) {
                v00 += ga[blo * 112 + c0]; v01 += ga[blo * 112 + c0 + 1];
                v10 += ga[bhi * 112 + c0]; v11 += ga[bhi * 112 + c0 + 1];
            }
            v00 = fmaxf(v00, 0.f); v01 = fmaxf(v01, 0.f);
            v10 = fmaxf(v10, 0.f); v11 = fmaxf(v11, 0.f);
            uint32_t hA, lA, hB, lB;
            pack_pair(v00, v01, hA, lA);
            pack_pair(v10, v11, hB, lB);
            const int p = c0 >> 1;
            DH[p * RS + rlo] = hA; DL[p * RS + rlo] = lA;
            DH[p * RS + rhi] = hB; DL[p * RS + rhi] = lB;
        }
    }
    __syncthreads();
}

// ============================================================================
// prep: pack weight images (ks-outer fragment order) + aw0 tail words
// ============================================================================
#define PREP_SLOTS 26496
#define PREP_TOTAL (PREP_SLOTS + 11200)
__global__ void vnet_prep(const float* m1w0, const float* m1w1, const float* m2w0,
                          const float* m2w1, const float* aw0, const float* aw1,
                          const float* m3w0, const float* m3w1, const float* m3w2) {
    const int i = blockIdx.x * blockDim.x + threadIdx.x;
    if (i >= PREP_TOTAL) return;
    if (i >= PREP_SLOTS) {
        const int j = i - PREP_SLOTS;
        const int k = j / 112, c = j - k * 112;
        const float v = (c < 100) ? aw0[(100 + k) * 100 + c] : 0.f;
        __nv_bfloat16 h = __float2bfloat16(v);
        __nv_bfloat16 l = __float2bfloat16(v - __bfloat162float(h));
        g_awt[j] = ((uint32_t)(*(uint16_t*)&h) << 16) | (uint32_t)(*(uint16_t*)&l);
        return;
    }
    const float* W; int K, N, T, off, lin;
    if      (i < 640)   { W = m1w0; K = 13;  N = 150; T = 20; off = IMG_L1;  lin = i; }
    else if (i < 5120)  { W = m1w1; K = 150; N = 100; T = 14; off = IMG_L2;  lin = i - 640; }
    else if (i < 8256)  { W = m2w0; K = 100; N = 100; T = 14; off = IMG_L3;  lin = i - 5120; }
    else if (i < 10048) { W = m2w1; K = 100; N = 50;  T = 8;  off = IMG_L4;  lin = i - 8256; }
    else if (i < 13184) { W = aw0;  K = 100; N = 100; T = 14; off = IMG_L5;  lin = i - 10048; }
    else if (i < 16320) { W = aw1;  K = 100; N = 100; T = 14; off = IMG_L6;  lin = i - 13184; }
    else if (i < 18880) { W = m3w0; K = 56;  N = 150; T = 20; off = IMG_M30; lin = i - 16320; }
    else if (i < 23360) { W = m3w1; K = 150; N = 100; T = 14; off = IMG_M31; lin = i - 18880; }
    else                { W = m3w2; K = 100; N = 100; T = 14; off = IMG_M32; lin = i - 23360; }
    const int l = lin & 31, q = lin >> 5;
    const int tn = q % T, ks = q / T;
    const int n = tn * 8 + (l >> 2), k0 = ks * 16 + (l & 3) * 2;
    float v[4];
#pragma unroll
    for (int j = 0; j < 4; ++j) {
        const int k = k0 + (j >> 1) * 8 + (j & 1);
        v[j] = (k < K && n < N) ? W[k * N + n] : 0.f;
    }
    uint32_t h0, l0, h1, l1;
    pack_pair(v[0], v[1], h0, l0);
    pack_pair(v[2], v[3], h1, l1);
    const size_t bo = (size_t)off + (size_t)lin * 8;
    *(uint32_t*)(g_wpack + bo) = h0;
    *(uint32_t*)(g_wpack + bo + 4) = h1;
    *(uint32_t*)(g_wpack + LO_BASE + bo) = l0;
    *(uint32_t*)(g_wpack + LO_BASE + bo + 4) = l1;
}

// ============================================================================
// kernel A: token-level net -> g_joint
// ============================================================================
__global__ __launch_bounds__(256, 2)
void vnet_a(const float* __restrict__ state,
            const float* __restrict__ m1b0, const float* __restrict__ m1b1,
            const float* __restrict__ m2b0, const float* __restrict__ m2b1,
            const float* __restrict__ ab0,  const float* __restrict__ ab1,
            const float* __restrict__ aw2,  const float* __restrict__ ab2,
            const int Btot) {
    extern __shared__ char pool[];
    const int tid = threadIdx.x;
    const int ctaB0 = blockIdx.x * NB;
    float* sBias = (float*)(pool + BIAS_A);

    // stage X [64 rows][8 pairs] + aw2 + m1b0
    {
        uint32_t* XH = (uint32_t*)(pool + SB_H);
        uint32_t* XL = (uint32_t*)(pool + SB_L);
        for (int idx = tid; idx < 64 * 8; idx += 256) {
            const int r = idx & 63, p = idx >> 6;
            const int b = r / NTOK, n = r - b * NTOK;
            const int gb = ctaB0 + b;
            float v0 = 0.f, v1 = 0.f;
            if (r < NB * NTOK && gb < Btot) {
                const float* sp = state + ((long)gb * NTOK + n) * D_IN;
                const int k0 = p * 2;
                if (k0 < D_IN) v0 = sp[k0];
                if (k0 + 1 < D_IN) v1 = sp[k0 + 1];
            }
            uint32_t h, l;
            pack_pair(v0, v1, h, l);
            XH[p * RS_A + r] = h;
            XL[p * RS_A + r] = l;
        }
        if (tid < 100) ((float*)(pool + AW2_A))[tid] = aw2[tid];
        if (tid < 160) sBias[tid] = (tid < 150) ? m1b0[tid] : 0.f;
    }

    // L1: X @ m1w0 -> h1 (slotA, Npad 160)
    run_layer<256, RS_A, 4, 10, 1, 20, 0>(pool, SB_H, SB_L, SA_H, SA_L,
        IMG_L1, WBUF_A, WCAP_A, BIAS_A, 0, 0, tid);

    if (tid < 112) sBias[tid] = (tid < 100) ? m1b1[tid] : 0.f;
    // L2: h1 @ m1w1 -> h (slotB, Npad 112), chunked 7+3
    run_layer<256, RS_A, 4, 7, 10, 14, 0>(pool, SA_H, SA_L, SB_H, SB_L,
        IMG_L2, WBUF_A, WCAP_A, BIAS_A, 0, 0, tid);

    // g = mean_n h
    {
        const uint32_t* HH = (const uint32_t*)(pool + SB_H);
        const uint32_t* HL = (const uint32_t*)(pool + SB_L);
        float* g = (float*)(pool + G_A);
        for (int idx = tid; idx < NB * 100; idx += 256) {
            const int b = idx / 100, k = idx - b * 100;
            const int p = k >> 1, odd = k & 1;
            float s = 0.f;
#pragma unroll
            for (int n = 0; n < NTOK; ++n) {
                const int w = p * RS_A + b * NTOK + n;
                s += odd ? (bf_hi(HH[w]) + bf_hi(HL[w]))
                         : (bf_lo(HH[w]) + bf_lo(HL[w]));
            }
            g[idx] = s * (1.f / NTOK);
        }
    }
    __syncthreads();

    // gatt from SMEM-staged aw0-tail words (2 chunks of 50 k)
    for (int c0 = 0; c0 < 100; c0 += 50) {
        stage_bytes<256>(pool, (const unsigned char*)(g_awt + c0 * 112),
                         WBUF_A, 50 * 112 * 4, tid);
        __syncthreads();
        const uint32_t* wv = (const uint32_t*)(pool + WBUF_A);
        float* ga = (float*)(pool + GATT_A);
        const float* g = (const float*)(pool + G_A);
        for (int idx = tid; idx < NB * 112; idx += 256) {
            const int b = idx / 112, c = idx - b * 112;
            float s = (c0 == 0) ? 0.f : ga[idx];
            const float* gp = g + b * 100 + c0;
#pragma unroll 5
            for (int k = 0; k < 50; ++k) {
                const uint32_t w = wv[k * 112 + c];
                s += gp[k] * (bf_hi(w) + bf_lo(w));
            }
            ga[idx] = s;
        }
        __syncthreads();
    }

    if (tid < 112) sBias[tid] = (tid < 100) ? ab0[tid] : 0.f;
    // L5: h @ aw0_head (+gatt) -> a1 (slotA)
    run_layer<256, RS_A, 4, 7, 7, 14, 1>(pool, SB_H, SB_L, SA_H, SA_L,
        IMG_L5, WBUF_A, WCAP_A, BIAS_A, GATT_A, 0, tid);

    if (tid < 112) sBias[tid] = (tid < 100) ? ab1[tid] : 0.f;
    // L6: a1 @ aw1 -> a2 (slotA in place; safe: stores after final sync)
    run_layer<256, RS_A, 4, 7, 7, 14, 0>(pool, SA_H, SA_L, SA_H, SA_L,
        IMG_L6, WBUF_A, WCAP_A, BIAS_A, 0, 0, tid);

    // attention scalar + zero weighted
    if (tid < 64) {
        float s = 0.f;
        if (tid < NB * NTOK) {
            s = ab2[0];
            const uint32_t* AH = (const uint32_t*)(pool + SA_H);
            const uint32_t* AL = (const uint32_t*)(pool + SA_L);
            const float* w = (const float*)(pool + AW2_A);
#pragma unroll 5
            for (int p = 0; p < 50; ++p) {
                const uint32_t uh = AH[p * RS_A + tid], ul = AL[p * RS_A + tid];
                s += (bf_lo(uh) + bf_lo(ul)) * w[2 * p]
                   + (bf_hi(uh) + bf_hi(ul)) * w[2 * p + 1];
            }
        }
        ((float*)(pool + ATT_A))[tid] = s;
    }
    if (tid < NB * 64) ((float*)(pool + WTD_A))[tid] = 0.f;
    __syncthreads();

    if (tid < 112) sBias[tid] = (tid < 100) ? m2b0[tid] : 0.f;
    // L3: h @ m2w0 -> f1 (slotA, a2 dead after att)
    run_layer<256, RS_A, 4, 7, 7, 14, 0>(pool, SB_H, SB_L, SA_H, SA_L,
        IMG_L3, WBUF_A, WCAP_A, BIAS_A, 0, 0, tid);

    if (tid < 64) sBias[tid] = (tid < 50) ? m2b1[tid] : 0.f;
    // L4: f1 @ m2w1, fused (f + bias)*att -> atomic weighted
    run_layer<256, RS_A, 4, 4, 7, 8, 2>(pool, SA_H, SA_L, 0, 0,
        IMG_L4, WBUF_A, WCAP_A, BIAS_A, ATT_A, WTD_A, tid);

    // joint -> global
    if (tid < NB * 56) {
        const int b = tid / 56, d = tid - b * 56;
        const int gb = ctaB0 + b;
        if (gb < Btot) {
            const float v = (d < 6) ? state[(long)gb * NTOK * D_IN + d]
                                    : ((const float*)(pool + WTD_A))[b * 64 + d - 6];
            g_joint[gb * 56 + d] = v;
        }
    }
}

// ============================================================================
// kernel B: m3 head GEMM over all batches (128 rows / CTA)
// ============================================================================
__global__ __launch_bounds__(512, 1)
void vnet_b(const float* __restrict__ m3b0, const float* __restrict__ m3b1,
            const float* __restrict__ m3b2, const float* __restrict__ m3w3,
            const float* __restrict__ m3b3, float* __restrict__ out,
            const int Btot) {
    extern __shared__ char pool[];
    const int tid = threadIdx.x;
    const int ctaB0 = blockIdx.x * 128;
    float* sBias = (float*)(pool + BIAS_B);

    {
        uint32_t* JH = (uint32_t*)(pool + BB_H);
        uint32_t* JL = (uint32_t*)(pool + BB_L);
        for (int idx = tid; idx < 128 * 32; idx += 512) {
            const int r = idx & 127, p = idx >> 7;
            const int gb = ctaB0 + r;
            float v0 = 0.f, v1 = 0.f;
            if (gb < Btot) {
                const int k0 = 2 * p;
                if (k0 < 56) v0 = g_joint[gb * 56 + k0];
                if (k0 + 1 < 56) v1 = g_joint[gb * 56 + k0 + 1];
            }
            uint32_t h, l;
            pack_pair(v0, v1, h, l);
            JH[p * RS_B + r] = h;
            JL[p * RS_B + r] = l;
        }
        if (tid < 100) ((float*)(pool + W3_B))[tid] = m3w3[tid];
        if (tid < 160) sBias[tid] = (tid < 150) ? m3b0[tid] : 0.f;
    }

    run_layer<512, RS_B, 8, 10, 4, 20, 0>(pool, BB_H, BB_L, BA_H, BA_L,
        IMG_M30, WBUF_B, WCAP_B, BIAS_B, 0, 0, tid);

    if (tid < 112) sBias[tid] = (tid < 100) ? m3b1[tid] : 0.f;
    run_layer<512, RS_B, 8, 7, 10, 14, 0>(pool, BA_H, BA_L, BA_H, BA_L,
        IMG_M31, WBUF_B, WCAP_B, BIAS_B, 0, 0, tid);

    if (tid < 112) sBias[tid] = (tid < 100) ? m3b2[tid] : 0.f;
    run_layer<512, RS_B, 8, 7, 7, 14, 0>(pool, BA_H, BA_L, BA_H, BA_L,
        IMG_M32, WBUF_B, WCAP_B, BIAS_B, 0, 0, tid);

    if (tid < 128) {
        const int gb = ctaB0 + tid;
        if (gb < Btot) {
            const uint32_t* AH = (const uint32_t*)(pool + BA_H);
            const uint32_t* AL = (const uint32_t*)(pool + BA_L);
            const float* w = (const float*)(pool + W3_B);
            float s = m3b3[0];
#pragma unroll 5
            for (int p = 0; p < 50; ++p) {
                const uint32_t uh = AH[p * RS_B + tid], ul = AL[p * RS_B + tid];
                s += (bf_lo(uh) + bf_lo(ul)) * w[2 * p]
                   + (bf_hi(uh) + bf_hi(ul)) * w[2 * p + 1];
            }
            out[gb] = s;
        }
    }
}

// ============================================================================
extern "C" void kernel_launch(void* const* d_in, const int* in_sizes, int n_in,
                              void* d_out, int out_size) {
    const float* state = (const float*)d_in[0];
    const float* m1w0 = (const float*)d_in[1],  *m1b0 = (const float*)d_in[2];
    const float* m1w1 = (const float*)d_in[3],  *m1b1 = (const float*)d_in[4];
    const float* m2w0 = (const float*)d_in[5],  *m2b0 = (const float*)d_in[6];
    const float* m2w1 = (const float*)d_in[7],  *m2b1 = (const float*)d_in[8];
    const float* aw0  = (const float*)d_in[9],  *ab0  = (const float*)d_in[10];
    const float* aw1  = (const float*)d_in[11], *ab1  = (const float*)d_in[12];
    const float* aw2  = (const float*)d_in[13], *ab2  = (const float*)d_in[14];
    const float* m3w0 = (const float*)d_in[15], *m3b0 = (const float*)d_in[16];
    const float* m3w1 = (const float*)d_in[17], *m3b1 = (const float*)d_in[18];
    const float* m3w2 = (const float*)d_in[19], *m3b2 = (const float*)d_in[20];
    const float* m3w3 = (const float*)d_in[21], *m3b3 = (const float*)d_in[22];
    float* out = (float*)d_out;
    const int Btot = in_sizes[0] / (NTOK * D_IN);

    static int attrSet = 0;
    if (!attrSet) {
        cudaFuncSetAttribute(vnet_a, cudaFuncAttributeMaxDynamicSharedMemorySize, SMEM_A);
        cudaFuncSetAttribute(vnet_b, cudaFuncAttributeMaxDynamicSharedMemorySize, SMEM_B);
        attrSet = 1;
    }

    vnet_prep<<<(PREP_TOTAL + 255) / 256, 256>>>(m1w0, m1w1, m2w0, m2w1, aw0, aw1,
                                                 m3w0, m3w1, m3w2);

    const int gridA = (Btot + NB - 1) / NB;
    vnet_a<<<gridA, 256, SMEM_A>>>(state, m1b0, m1b1, m2b0, m2b1,
                                   ab0, ab1, aw2, ab2, Btot);

    const int gridB = (Btot + 127) / 128;
    vnet_b<<<gridB, 512, SMEM_B>>>(m3b0, m3b1, m3b2, m3w3, m3b3, out, Btot);
}

// round 10
// speedup vs baseline: 3.4221x; 1.3073x over previous
#include <cuda_runtime.h>
#include <cuda_fp16.h>
#include <cstdint>

// ============================================================================
// ValueNetwork via mma.sync m16n8k16 fp16 (A 2-term split, B single f16).
// Kernel A (token net): 256 thr, NB=3 batches (M=64 rows), 2 CTAs/SM.
// Kernel B (m3 head):   512 thr, 128 batches/CTA (M=128), 1 wave GEMM.
// Weight images packed ks-outer in B-fragment lane order.
// ============================================================================

#define NTOK 20
#define D_IN 13
#define NB 3

// ---- packed weight images (bytes, f16 fragments) ----
#define IMG_L1  0        // m1w0: TILES20 NK1   (5120 B)
#define IMG_L2  5120     // m1w1: TILES14 NK10  (35840)
#define IMG_L3  40960    // m2w0: TILES14 NK7   (25088)
#define IMG_L4  66048    // m2w1: TILES8  NK7   (14336)
#define IMG_L5  80384    // aw0 head: T14 NK7   (25088)
#define IMG_L6  105472   // aw1: T14 NK7        (25088)
#define IMG_M30 130560   // m3w0: T20 NK4       (20480)
#define IMG_M31 151040   // m3w1: T14 NK10      (35840)
#define IMG_M32 186880   // m3w2: T14 NK7       (25088)
#define IMG_TOTAL 211968
__device__ __align__(16) unsigned char g_wpack[IMG_TOTAL];
__device__ __align__(16) float g_awt[100 * 112];      // aw0 tail, fp32
__device__ __align__(16) float g_joint[16384 * 56];   // inter-kernel scratch

// ---- kernel A SMEM (bytes), RS_A = 72 words ----
#define RS_A 72
#define SA_H 0          // 80 pairs * 72 * 4 = 23040
#define SA_L 23040
#define SB_H 46080      // 56 pairs -> 16128
#define SB_L 62208
#define WBUF_A 78336    // 25088
#define WCAP_A 25088
#define BIAS_A 103424
#define G_A    104064
#define GATT_A 105264
#define ATT_A  106608
#define AW2_A  106864
#define WTD_A  107264
#define SMEM_A 108032

// ---- kernel B SMEM, RS_B = 136 words ----
#define RS_B 136
#define BA_H 0          // 80 pairs * 136 * 4 = 43520
#define BA_L 43520
#define BB_H 87040      // 32 pairs -> 17408
#define BB_L 104448
#define WBUF_B 121856   // 35840
#define WCAP_B 35840
#define BIAS_B 157696
#define W3_B   158336
#define SMEM_B 158736

// ============================================================================
__device__ __forceinline__ uint16_t f16bits(float v) {
    __half h = __float2half_rn(v);
    return __half_as_ushort(h);
}
// A-activation pack: hi word = f16(v0)|f16(v1), lo word = f16 residuals
__device__ __forceinline__ void pack_pair(float v0, float v1,
                                          uint32_t& hi, uint32_t& lo) {
    __half h0 = __float2half_rn(v0), h1 = __float2half_rn(v1);
    float r0 = v0 - __half2float(h0), r1 = v1 - __half2float(h1);
    hi = ((uint32_t)__half_as_ushort(h1) << 16) | __half_as_ushort(h0);
    lo = ((uint32_t)f16bits(r1) << 16) | f16bits(r0);
}
__device__ __forceinline__ float f16lo(uint32_t u) {
    return __half2float(__ushort_as_half((uint16_t)(u & 0xFFFF)));
}
__device__ __forceinline__ float f16hi(uint32_t u) {
    return __half2float(__ushort_as_half((uint16_t)(u >> 16)));
}

__device__ __forceinline__ void hmma4(float* a, uint32_t a0, uint32_t a1,
                                      uint32_t a2, uint32_t a3, uint2 b) {
    asm volatile(
        "mma.sync.aligned.m16n8k16.row.col.f32.f16.f16.f32 "
        "{%0,%1,%2,%3}, {%4,%5,%6,%7}, {%8,%9}, {%0,%1,%2,%3};"
        : "+f"(a[0]), "+f"(a[1]), "+f"(a[2]), "+f"(a[3])
        : "r"(a0), "r"(a1), "r"(a2), "r"(a3), "r"(b.x), "r"(b.y));
}

template <int NTHR>
__device__ __forceinline__ void stage_bytes(char* pool, const unsigned char* src,
                                            int dstOff, int bytes, int tid) {
    float4* d = (float4*)(pool + dstOff);
    const float4* s = (const float4*)src;
    const int n = bytes >> 4;
    for (int i = tid; i < n; i += NTHR) d[i] = s[i];
}

// one K-chunk: per ks load Ah+Al fragments once, per tile load B fragment once,
// issue 2 HMMAs (Ah*B, Al*B).
template <int NT, int TILES, int RS>
__device__ __forceinline__ void mma_chunk(const char* pool, int srcH, int srcL,
                                          int wbufOff, float (*acc)[4],
                                          int ks0, int nks, int mt, int nh, int lane) {
    const uint32_t* AH = (const uint32_t*)(pool + srcH);
    const uint32_t* AL = (const uint32_t*)(pool + srcL);
    const uint2* Bv = (const uint2*)(pool + wbufOff);
    const int lm = lane & 3, r0 = mt * 16 + (lane >> 2);
    for (int ksl = 0; ksl < nks; ++ksl) {
        const int p0 = (ks0 + ksl) * 8 + lm;
        const uint32_t ah0 = AH[p0 * RS + r0], ah1 = AH[p0 * RS + r0 + 8];
        const uint32_t ah2 = AH[(p0 + 4) * RS + r0], ah3 = AH[(p0 + 4) * RS + r0 + 8];
        const uint32_t al0 = AL[p0 * RS + r0], al1 = AL[p0 * RS + r0 + 8];
        const uint32_t al2 = AL[(p0 + 4) * RS + r0], al3 = AL[(p0 + 4) * RS + r0 + 8];
#pragma unroll
        for (int t = 0; t < NT; ++t) {
            const uint2 b = Bv[(ksl * TILES + nh * NT + t) * 32 + lane];
            hmma4(acc[t], ah0, ah1, ah2, ah3, b);
            hmma4(acc[t], al0, al1, al2, al3, b);
        }
    }
}

// full fused layer. EPI: 0 = relu->pairs, 1 = relu+gatt->pairs, 2 = f*att atomic.
template <int NTHR, int RS, int MTILES, int NT, int NK, int TILES, int EPI>
__device__ void run_layer(char* pool, int srcH, int srcL, int dstH, int dstL,
                          int imgOff, int wbufOff, int wbufCap,
                          int biasOff, int auxOff, int aux2Off, int tid) {
    const int wid = tid >> 5, lane = tid & 31;
    const int mt = wid % MTILES, nh = wid / MTILES;
    float acc[NT][4];
#pragma unroll
    for (int t = 0; t < NT; ++t)
        acc[t][0] = acc[t][1] = acc[t][2] = acc[t][3] = 0.f;
    const int bpk = TILES * 256;
    const int ksCap = wbufCap / bpk;
    for (int k0 = 0; k0 < NK; k0 += ksCap) {
        const int nks = (NK - k0 < ksCap) ? NK - k0 : ksCap;
        stage_bytes<NTHR>(pool, g_wpack + imgOff + (size_t)k0 * bpk, wbufOff,
                          nks * bpk, tid);
        __syncthreads();
        mma_chunk<NT, TILES, RS>(pool, srcH, srcL, wbufOff, acc, k0, nks, mt, nh, lane);
        __syncthreads();
    }
    const float* bias = (const float*)(pool + biasOff);
    const int rlo = mt * 16 + (lane >> 2), rhi = rlo + 8;
    if (EPI == 2) {
        const float* att = (const float*)(pool + auxOff);
        float* wtd = (float*)(pool + aux2Off);
        const float alo = att[rlo], ahi = att[rhi];
        int blo = rlo / NTOK; if (blo > NB - 1) blo = NB - 1;
        int bhi = rhi / NTOK; if (bhi > NB - 1) bhi = NB - 1;
#pragma unroll
        for (int t = 0; t < NT; ++t) {
            const int c0 = (nh * NT + t) * 8 + (lane & 3) * 2;
            if (c0 < 50) {
                atomicAdd(&wtd[blo * 64 + c0], (acc[t][0] + bias[c0]) * alo);
                atomicAdd(&wtd[bhi * 64 + c0], (acc[t][2] + bias[c0]) * ahi);
            }
            if (c0 + 1 < 50) {
                atomicAdd(&wtd[blo * 64 + c0 + 1], (acc[t][1] + bias[c0 + 1]) * alo);
                atomicAdd(&wtd[bhi * 64 + c0 + 1], (acc[t][3] + bias[c0 + 1]) * ahi);
            }
        }
    } else {
        const float* ga = (const float*)(pool + auxOff);
        int blo = 0, bhi = 0;
        if (EPI == 1) {
            blo = rlo / NTOK; if (blo > NB - 1) blo = NB - 1;
            bhi = rhi / NTOK; if (bhi > NB - 1) bhi = NB - 1;
        }
        uint32_t* DH = (uint32_t*)(pool + dstH);
        uint32_t* DL = (uint32_t*)(pool + dstL);
#pragma unroll
        for (int t = 0; t < NT; ++t) {
            const int c0 = (nh * NT + t) * 8 + (lane & 3) * 2;
            float v00 = acc[t][0] + bias[c0], v01 = acc[t][1] + bias[c0 + 1];
            float v10 = acc[t][2] + bias[c0], v11 = acc[t][3] + bias[c0 + 1];
            if (EPI == 1) {
                v00 += ga[blo * 112 + c0]; v01 += ga[blo * 112 + c0 + 1];
                v10 += ga[bhi * 112 + c0]; v11 += ga[bhi * 112 + c0 + 1];
            }
            v00 = fmaxf(v00, 0.f); v01 = fmaxf(v01, 0.f);
            v10 = fmaxf(v10, 0.f); v11 = fmaxf(v11, 0.f);
            uint32_t hA, lA, hB, lB;
            pack_pair(v00, v01, hA, lA);
            pack_pair(v10, v11, hB, lB);
            const int p = c0 >> 1;
            DH[p * RS + rlo] = hA; DL[p * RS + rlo] = lA;
            DH[p * RS + rhi] = hB; DL[p * RS + rhi] = lB;
        }
    }
    __syncthreads();
}

// ============================================================================
// prep: pack weight images (ks-outer, f16 fragments) + aw0 tail fp32
// ============================================================================
#define PREP_SLOTS 26496
#define PREP_TOTAL (PREP_SLOTS + 11200)
__global__ void vnet_prep(const float* m1w0, const float* m1w1, const float* m2w0,
                          const float* m2w1, const float* aw0, const float* aw1,
                          const float* m3w0, const float* m3w1, const float* m3w2) {
    const int i = blockIdx.x * blockDim.x + threadIdx.x;
    if (i >= PREP_TOTAL) return;
    if (i >= PREP_SLOTS) {
        const int j = i - PREP_SLOTS;
        const int k = j / 112, c = j - k * 112;
        g_awt[j] = (c < 100) ? aw0[(100 + k) * 100 + c] : 0.f;
        return;
    }
    const float* W; int K, N, T, off, lin;
    if      (i < 640)   { W = m1w0; K = 13;  N = 150; T = 20; off = IMG_L1;  lin = i; }
    else if (i < 5120)  { W = m1w1; K = 150; N = 100; T = 14; off = IMG_L2;  lin = i - 640; }
    else if (i < 8256)  { W = m2w0; K = 100; N = 100; T = 14; off = IMG_L3;  lin = i - 5120; }
    else if (i < 10048) { W = m2w1; K = 100; N = 50;  T = 8;  off = IMG_L4;  lin = i - 8256; }
    else if (i < 13184) { W = aw0;  K = 100; N = 100; T = 14; off = IMG_L5;  lin = i - 10048; }
    else if (i < 16320) { W = aw1;  K = 100; N = 100; T = 14; off = IMG_L6;  lin = i - 13184; }
    else if (i < 18880) { W = m3w0; K = 56;  N = 150; T = 20; off = IMG_M30; lin = i - 16320; }
    else if (i < 23360) { W = m3w1; K = 150; N = 100; T = 14; off = IMG_M31; lin = i - 18880; }
    else                { W = m3w2; K = 100; N = 100; T = 14; off = IMG_M32; lin = i - 23360; }
    const int l = lin & 31, q = lin >> 5;
    const int tn = q % T, ks = q / T;
    const int n = tn * 8 + (l >> 2), k0 = ks * 16 + (l & 3) * 2;
    float v[4];
#pragma unroll
    for (int j = 0; j < 4; ++j) {
        const int k = k0 + (j >> 1) * 8 + (j & 1);
        v[j] = (k < K && n < N) ? W[k * N + n] : 0.f;
    }
    const uint32_t x = ((uint32_t)f16bits(v[1]) << 16) | f16bits(v[0]);
    const uint32_t y = ((uint32_t)f16bits(v[3]) << 16) | f16bits(v[2]);
    const size_t bo = (size_t)off + (size_t)lin * 8;
    *(uint32_t*)(g_wpack + bo) = x;
    *(uint32_t*)(g_wpack + bo + 4) = y;
}

// ============================================================================
// kernel A: token-level net -> g_joint
// ============================================================================
__global__ __launch_bounds__(256, 2)
void vnet_a(const float* __restrict__ state,
            const float* __restrict__ m1b0, const float* __restrict__ m1b1,
            const float* __restrict__ m2b0, const float* __restrict__ m2b1,
            const float* __restrict__ ab0,  const float* __restrict__ ab1,
            const float* __restrict__ aw2,  const float* __restrict__ ab2,
            const int Btot) {
    extern __shared__ char pool[];
    const int tid = threadIdx.x;
    const int ctaB0 = blockIdx.x * NB;
    float* sBias = (float*)(pool + BIAS_A);

    // stage X [64 rows][8 pairs] + aw2 + m1b0
    {
        uint32_t* XH = (uint32_t*)(pool + SB_H);
        uint32_t* XL = (uint32_t*)(pool + SB_L);
        for (int idx = tid; idx < 64 * 8; idx += 256) {
            const int r = idx & 63, p = idx >> 6;
            const int b = r / NTOK, n = r - b * NTOK;
            const int gb = ctaB0 + b;
            float v0 = 0.f, v1 = 0.f;
            if (r < NB * NTOK && gb < Btot) {
                const float* sp = state + ((long)gb * NTOK + n) * D_IN;
                const int k0 = p * 2;
                if (k0 < D_IN) v0 = sp[k0];
                if (k0 + 1 < D_IN) v1 = sp[k0 + 1];
            }
            uint32_t h, l;
            pack_pair(v0, v1, h, l);
            XH[p * RS_A + r] = h;
            XL[p * RS_A + r] = l;
        }
        if (tid < 100) ((float*)(pool + AW2_A))[tid] = aw2[tid];
        if (tid < 160) sBias[tid] = (tid < 150) ? m1b0[tid] : 0.f;
    }

    // L1: X @ m1w0 -> h1 (slotA, Npad 160)
    run_layer<256, RS_A, 4, 10, 1, 20, 0>(pool, SB_H, SB_L, SA_H, SA_L,
        IMG_L1, WBUF_A, WCAP_A, BIAS_A, 0, 0, tid);

    if (tid < 112) sBias[tid] = (tid < 100) ? m1b1[tid] : 0.f;
    // L2: h1 @ m1w1 -> h (slotB, Npad 112), chunked 7+3
    run_layer<256, RS_A, 4, 7, 10, 14, 0>(pool, SA_H, SA_L, SB_H, SB_L,
        IMG_L2, WBUF_A, WCAP_A, BIAS_A, 0, 0, tid);

    // g = mean_n h
    {
        const uint32_t* HH = (const uint32_t*)(pool + SB_H);
        const uint32_t* HL = (const uint32_t*)(pool + SB_L);
        float* g = (float*)(pool + G_A);
        for (int idx = tid; idx < NB * 100; idx += 256) {
            const int b = idx / 100, k = idx - b * 100;
            const int p = k >> 1, odd = k & 1;
            float s = 0.f;
#pragma unroll
            for (int n = 0; n < NTOK; ++n) {
                const int w = p * RS_A + b * NTOK + n;
                s += odd ? (f16hi(HH[w]) + f16hi(HL[w]))
                         : (f16lo(HH[w]) + f16lo(HL[w]));
            }
            g[idx] = s * (1.f / NTOK);
        }
    }
    __syncthreads();

    // gatt from SMEM-staged fp32 aw0-tail (2 chunks of 50 k-rows)
    for (int c0 = 0; c0 < 100; c0 += 50) {
        stage_bytes<256>(pool, (const unsigned char*)(g_awt + c0 * 112),
                         WBUF_A, 50 * 112 * 4, tid);
        __syncthreads();
        const float* wf = (const float*)(pool + WBUF_A);
        float* ga = (float*)(pool + GATT_A);
        const float* g = (const float*)(pool + G_A);
        for (int idx = tid; idx < NB * 112; idx += 256) {
            const int b = idx / 112, c = idx - b * 112;
            float s = (c0 == 0) ? 0.f : ga[idx];
            const float* gp = g + b * 100 + c0;
#pragma unroll 5
            for (int k = 0; k < 50; ++k) s += gp[k] * wf[k * 112 + c];
            ga[idx] = s;
        }
        __syncthreads();
    }

    if (tid < 112) sBias[tid] = (tid < 100) ? ab0[tid] : 0.f;
    // L5: h @ aw0_head (+gatt) -> a1 (slotA)
    run_layer<256, RS_A, 4, 7, 7, 14, 1>(pool, SB_H, SB_L, SA_H, SA_L,
        IMG_L5, WBUF_A, WCAP_A, BIAS_A, GATT_A, 0, tid);

    if (tid < 112) sBias[tid] = (tid < 100) ? ab1[tid] : 0.f;
    // L6: a1 @ aw1 -> a2 (slotA in place)
    run_layer<256, RS_A, 4, 7, 7, 14, 0>(pool, SA_H, SA_L, SA_H, SA_L,
        IMG_L6, WBUF_A, WCAP_A, BIAS_A, 0, 0, tid);

    // attention scalar + zero weighted
    if (tid < 64) {
        float s = 0.f;
        if (tid < NB * NTOK) {
            s = ab2[0];
            const uint32_t* AH = (const uint32_t*)(pool + SA_H);
            const uint32_t* AL = (const uint32_t*)(pool + SA_L);
            const float* w = (const float*)(pool + AW2_A);
#pragma unroll 5
            for (int p = 0; p < 50; ++p) {
                const uint32_t uh = AH[p * RS_A + tid], ul = AL[p * RS_A + tid];
                s += (f16lo(uh) + f16lo(ul)) * w[2 * p]
                   + (f16hi(uh) + f16hi(ul)) * w[2 * p + 1];
            }
        }
        ((float*)(pool + ATT_A))[tid] = s;
    }
    if (tid < NB * 64) ((float*)(pool + WTD_A))[tid] = 0.f;
    __syncthreads();

    if (tid < 112) sBias[tid] = (tid < 100) ? m2b0[tid] : 0.f;
    // L3: h @ m2w0 -> f1 (slotA, a2 dead after att)
    run_layer<256, RS_A, 4, 7, 7, 14, 0>(pool, SB_H, SB_L, SA_H, SA_L,
        IMG_L3, WBUF_A, WCAP_A, BIAS_A, 0, 0, tid);

    if (tid < 64) sBias[tid] = (tid < 50) ? m2b1[tid] : 0.f;
    // L4: f1 @ m2w1, fused (f + bias)*att -> atomic weighted
    run_layer<256, RS_A, 4, 4, 7, 8, 2>(pool, SA_H, SA_L, 0, 0,
        IMG_L4, WBUF_A, WCAP_A, BIAS_A, ATT_A, WTD_A, tid);

    // joint -> global
    if (tid < NB * 56) {
        const int b = tid / 56, d = tid - b * 56;
        const int gb = ctaB0 + b;
        if (gb < Btot) {
            const float v = (d < 6) ? state[(long)gb * NTOK * D_IN + d]
                                    : ((const float*)(pool + WTD_A))[b * 64 + d - 6];
            g_joint[gb * 56 + d] = v;
        }
    }
}

// ============================================================================
// kernel B: m3 head GEMM over all batches (128 rows / CTA)
// ============================================================================
__global__ __launch_bounds__(512, 1)
void vnet_b(const float* __restrict__ m3b0, const float* __restrict__ m3b1,
            const float* __restrict__ m3b2, const float* __restrict__ m3w3,
            const float* __restrict__ m3b3, float* __restrict__ out,
            const int Btot) {
    extern __shared__ char pool[];
    const int tid = threadIdx.x;
    const int ctaB0 = blockIdx.x * 128;
    float* sBias = (float*)(pool + BIAS_B);

    {
        uint32_t* JH = (uint32_t*)(pool + BB_H);
        uint32_t* JL = (uint32_t*)(pool + BB_L);
        for (int idx = tid; idx < 128 * 32; idx += 512) {
            const int r = idx & 127, p = idx >> 7;
            const int gb = ctaB0 + r;
            float v0 = 0.f, v1 = 0.f;
            if (gb < Btot) {
                const int k0 = 2 * p;
                if (k0 < 56) v0 = g_joint[gb * 56 + k0];
                if (k0 + 1 < 56) v1 = g_joint[gb * 56 + k0 + 1];
            }
            uint32_t h, l;
            pack_pair(v0, v1, h, l);
            JH[p * RS_B + r] = h;
            JL[p * RS_B + r] = l;
        }
        if (tid < 100) ((float*)(pool + W3_B))[tid] = m3w3[tid];
        if (tid < 160) sBias[tid] = (tid < 150) ? m3b0[tid] : 0.f;
    }

    run_layer<512, RS_B, 8, 10, 4, 20, 0>(pool, BB_H, BB_L, BA_H, BA_L,
        IMG_M30, WBUF_B, WCAP_B, BIAS_B, 0, 0, tid);

    if (tid < 112) sBias[tid] = (tid < 100) ? m3b1[tid] : 0.f;
    run_layer<512, RS_B, 8, 7, 10, 14, 0>(pool, BA_H, BA_L, BA_H, BA_L,
        IMG_M31, WBUF_B, WCAP_B, BIAS_B, 0, 0, tid);

    if (tid < 112) sBias[tid] = (tid < 100) ? m3b2[tid] : 0.f;
    run_layer<512, RS_B, 8, 7, 7, 14, 0>(pool, BA_H, BA_L, BA_H, BA_L,
        IMG_M32, WBUF_B, WCAP_B, BIAS_B, 0, 0, tid);

    if (tid < 128) {
        const int gb = ctaB0 + tid;
        if (gb < Btot) {
            const uint32_t* AH = (const uint32_t*)(pool + BA_H);
            const uint32_t* AL = (const uint32_t*)(pool + BA_L);
            const float* w = (const float*)(pool + W3_B);
            float s = m3b3[0];
#pragma unroll 5
            for (int p = 0; p < 50; ++p) {
                const uint32_t uh = AH[p * RS_B + tid], ul = AL[p * RS_B + tid];
                s += (f16lo(uh) + f16lo(ul)) * w[2 * p]
                   + (f16hi(uh) + f16hi(ul)) * w[2 * p + 1];
            }
            out[gb] = s;
        }
    }
}

// ============================================================================
extern "C" void kernel_launch(void* const* d_in, const int* in_sizes, int n_in,
                              void* d_out, int out_size) {
    const float* state = (const float*)d_in[0];
    const float* m1w0 = (const float*)d_in[1],  *m1b0 = (const float*)d_in[2];
    const float* m1w1 = (const float*)d_in[3],  *m1b1 = (const float*)d_in[4];
    const float* m2w0 = (const float*)d_in[5],  *m2b0 = (const float*)d_in[6];
    const float* m2w1 = (const float*)d_in[7],  *m2b1 = (const float*)d_in[8];
    const float* aw0  = (const float*)d_in[9],  *ab0  = (const float*)d_in[10];
    const float* aw1  = (const float*)d_in[11], *ab1  = (const float*)d_in[12];
    const float* aw2  = (const float*)d_in[13], *ab2  = (const float*)d_in[14];
    const float* m3w0 = (const float*)d_in[15], *m3b0 = (const float*)d_in[16];
    const float* m3w1 = (const float*)d_in[17], *m3b1 = (const float*)d_in[18];
    const float* m3w2 = (const float*)d_in[19], *m3b2 = (const float*)d_in[20];
    const float* m3w3 = (const float*)d_in[21], *m3b3 = (const float*)d_in[22];
    float* out = (float*)d_out;
    const int Btot = in_sizes[0] / (NTOK * D_IN);

    static int attrSet = 0;
    if (!attrSet) {
        cudaFuncSetAttribute(vnet_a, cudaFuncAttributeMaxDynamicSharedMemorySize, SMEM_A);
        cudaFuncSetAttribute(vnet_b, cudaFuncAttributeMaxDynamicSharedMemorySize, SMEM_B);
        attrSet = 1;
    }

    vnet_prep<<<(PREP_TOTAL + 255) / 256, 256>>>(m1w0, m1w1, m2w0, m2w1, aw0, aw1,
                                                 m3w0, m3w1, m3w2);

    const int gridA = (Btot + NB - 1) / NB;
    vnet_a<<<gridA, 256, SMEM_A>>>(state, m1b0, m1b1, m2b0, m2b1,
                                   ab0, ab1, aw2, ab2, Btot);

    const int gridB = (Btot + 127) / 128;
    vnet_b<<<gridB, 512, SMEM_B>>>(m3b0, m3b1, m3b2, m3w3, m3b3, out, Btot);
}